// round 1
// baseline (speedup 1.0000x reference)
#include <cuda_runtime.h>

#define BB   2
#define CFI  32
#define HH   192
#define WWD  192
#define NN   (HH*WWD)        // 36864
#define NUMK 16
#define CT   67
#define EPSL 1e-5f
#define TS   256
#define NT   (NN/TS)         // 144

// ---------------- scratch (static device globals; no allocation) ----------------
__device__ float g_P[BB*NN*CFI];        // [b][n][c]  folded W1[:,0:32] @ If
__device__ float g_Q[BB*NN*CFI];        // [b][n][c]  folded W1[:,32:64] @ If
__device__ float g_U[BB*NUMK*NN];       // (Alpha+1)*Pfnum + Beta
__device__ float g_Om[BB*NUMK*NN];      // Omega logits

__device__ float g_WPQ[64*32];          // rows 0..31: P weights, 32..63: Q weights (BN-folded)
__device__ float g_w1p[32], g_w1a[32], g_w1b[32], g_t1[32];
__device__ float g_W2t[32*32], g_t2[32];   // transposed [k][c], BN-folded
__device__ float g_W3t[32*32], g_t3[32];
__device__ float g_W4t[32*32], g_t4[32];
__device__ float g_wcA[32], g_wcB[32], g_wcC[32];
__device__ float g_bcv[3];
__device__ int   g_args64;              // 1 if args buffer is int64, 0 if int32

__device__ __forceinline__ float gelu_f(float x) {
    return 0.5f * x * (1.0f + erff(x * 0.70710678118654752f));
}

// ---------------- kernel 1: fold BN into weights, detect args dtype ----------------
__global__ void prep_kernel(
    const float* __restrict__ W1, const float* __restrict__ g1, const float* __restrict__ b1,
    const float* __restrict__ m1, const float* __restrict__ v1,
    const float* __restrict__ W2, const float* __restrict__ g2, const float* __restrict__ b2,
    const float* __restrict__ m2, const float* __restrict__ v2,
    const float* __restrict__ W3, const float* __restrict__ g3, const float* __restrict__ b3,
    const float* __restrict__ m3, const float* __restrict__ v3,
    const float* __restrict__ W4, const float* __restrict__ g4, const float* __restrict__ b4,
    const float* __restrict__ m4, const float* __restrict__ v4,
    const float* __restrict__ Wc, const float* __restrict__ bc,
    const int*   __restrict__ args_i32)
{
    __shared__ float inv1[32], inv2[32], inv3[32], inv4[32];
    int t = threadIdx.x;
    if (t < 32) {
        float i1 = g1[t]*rsqrtf(v1[t]+EPSL); inv1[t]=i1; g_t1[t]=b1[t]-m1[t]*i1;
        float i2 = g2[t]*rsqrtf(v2[t]+EPSL); inv2[t]=i2; g_t2[t]=b2[t]-m2[t]*i2;
        float i3 = g3[t]*rsqrtf(v3[t]+EPSL); inv3[t]=i3; g_t3[t]=b3[t]-m3[t]*i3;
        float i4 = g4[t]*rsqrtf(v4[t]+EPSL); inv4[t]=i4; g_t4[t]=b4[t]-m4[t]*i4;
        g_wcA[t]=Wc[t]; g_wcB[t]=Wc[32+t]; g_wcC[t]=Wc[64+t];
        g_w1p[t]=W1[t*CT+64]*i1; g_w1a[t]=W1[t*CT+65]*i1; g_w1b[t]=W1[t*CT+66]*i1;
    }
    if (t < 3) g_bcv[t] = bc[t];
    if (t == 0) {
        // If dtype is int64 (little-endian), every odd 32-bit word is 0 (values < 2^31).
        // 128 random values in [0,36864) being all zero is impossible for int32.
        int all_zero = 1;
        for (int i = 0; i < 128; i++) if (args_i32[2*i+1] != 0) { all_zero = 0; break; }
        g_args64 = all_zero;
    }
    __syncthreads();
    for (int idx = t; idx < 2048; idx += blockDim.x) {
        int r = idx >> 5, i = idx & 31;
        g_WPQ[idx] = (r < 32) ? W1[r*CT + i] * inv1[r]
                              : W1[(r-32)*CT + 32 + i] * inv1[r-32];
    }
    for (int idx = t; idx < 1024; idx += blockDim.x) {
        int kk = idx >> 5, c = idx & 31;
        g_W2t[idx] = W2[c*32+kk] * inv2[c];
        g_W3t[idx] = W3[c*32+kk] * inv3[c];
        g_W4t[idx] = W4[c*32+kk] * inv4[c];
    }
}

// ---------------- kernel 2: P/Q = folded-W1 @ If, written [b][n][c] ----------------
__global__ void pq_kernel(const float* __restrict__ If)
{
    __shared__ float wf[2048];
    __shared__ float tb[256*33];          // padded to kill STS bank conflicts
    int tid  = threadIdx.x;
    int b    = blockIdx.x / NT;
    int tile = blockIdx.x % NT;
    int n0   = tile * 256;

    for (int idx = tid; idx < 2048; idx += 256) wf[idx] = g_WPQ[idx];

    int n = n0 + tid;
    float x[32];
    #pragma unroll
    for (int i = 0; i < 32; i++) x[i] = If[((size_t)b*32 + i)*NN + n];
    __syncthreads();

    size_t base = ((size_t)b*NN + n0) * 32;

    // P
    #pragma unroll
    for (int c = 0; c < 32; c++) {
        float acc = 0.f;
        #pragma unroll
        for (int i = 0; i < 32; i += 4) {
            float4 w = *(const float4*)&wf[c*32 + i];
            acc += w.x*x[i] + w.y*x[i+1] + w.z*x[i+2] + w.w*x[i+3];
        }
        tb[tid*33 + c] = acc;
    }
    __syncthreads();
    for (int idx = tid; idx < 8192; idx += 256)
        g_P[base + idx] = tb[(idx >> 5)*33 + (idx & 31)];
    __syncthreads();

    // Q
    #pragma unroll
    for (int c = 0; c < 32; c++) {
        float acc = 0.f;
        #pragma unroll
        for (int i = 0; i < 32; i += 4) {
            float4 w = *(const float4*)&wf[(32+c)*32 + i];
            acc += w.x*x[i] + w.y*x[i+1] + w.z*x[i+2] + w.w*x[i+3];
        }
        tb[tid*33 + c] = acc;
    }
    __syncthreads();
    for (int idx = tid; idx < 8192; idx += 256)
        g_Q[base + idx] = tb[(idx >> 5)*33 + (idx & 31)];
}

// ---------------- fused MLP layer: dst[c][s] = act(Wt^T src + bias [+ addsrc]) ----------------
template<bool ADD>
__device__ __forceinline__ void mlp_layer(
    const float* __restrict__ src, float* __restrict__ dst,
    const float* __restrict__ Wt, const float* __restrict__ bias,
    const float* __restrict__ addsrc, int cg, int sg)
{
    int c0 = cg * 4;
    float4 tv = *(const float4*)&bias[c0];
    float acc0[8], acc1[8], acc2[8], acc3[8];
    #pragma unroll
    for (int u = 0; u < 8; u++) { acc0[u]=tv.x; acc1[u]=tv.y; acc2[u]=tv.z; acc3[u]=tv.w; }
    #pragma unroll
    for (int kk = 0; kk < 32; kk++) {
        float4 w = __ldg((const float4*)Wt + kk*8 + cg);   // broadcast, L1-hot
        #pragma unroll
        for (int u = 0; u < 8; u++) {
            float a = src[kk*TS + sg + 32*u];              // conflict-free LDS
            acc0[u] += w.x*a; acc1[u] += w.y*a; acc2[u] += w.z*a; acc3[u] += w.w*a;
        }
    }
    #pragma unroll
    for (int u = 0; u < 8; u++) {
        int s = sg + 32*u;
        float v0 = acc0[u], v1 = acc1[u], v2 = acc2[u], v3 = acc3[u];
        if (ADD) {
            v0 += addsrc[(c0+0)*TS+s]; v1 += addsrc[(c0+1)*TS+s];
            v2 += addsrc[(c0+2)*TS+s]; v3 += addsrc[(c0+3)*TS+s];
        }
        dst[(c0+0)*TS+s] = gelu_f(v0);
        dst[(c0+1)*TS+s] = gelu_f(v1);
        dst[(c0+2)*TS+s] = gelu_f(v2);
        dst[(c0+3)*TS+s] = gelu_f(v3);
    }
}

// ---------------- kernel 3: main fused MLP over 256-sample tiles ----------------
__global__ void __launch_bounds__(256, 2) main_kernel(
    const float* __restrict__ Pf,
    const float* __restrict__ Of,
    const void*  __restrict__ args)
{
    extern __shared__ float sm[];
    float* buf0 = sm;             // 32x256
    float* buf1 = sm + 8192;
    float* buf2 = sm + 16384;
    int*   jj   = (int*)(sm + 24576);
    float* pfv  = sm + 24832;

    int bk   = blockIdx.x / NT;
    int tile = blockIdx.x % NT;
    int b = bk / NUMK, k = bk % NUMK;
    int n0 = tile * TS;
    int tid = threadIdx.x;
    int cg = tid >> 5, sg = tid & 31;
    int c0 = cg * 4;

    // stage 0: per-sample gather index + Pf gather
    {
        size_t ai = ((size_t)(b*NUMK + k))*NN + n0 + tid;
        long long j;
        if (g_args64) j = ((const long long*)args)[ai];
        else          j = ((const int*)args)[ai];
        jj[tid]  = (int)j;
        pfv[tid] = Pf[(size_t)b*NN + (int)j];
    }
    __syncthreads();

    // stage 1: z1 = P[n] + Q[j] + w1p*Pf[j] + w1a*Of0 + w1b*Of1 + t1 ; h1 = gelu(z1)
    {
        const float4* P4 = (const float4*)g_P;
        const float4* Q4 = (const float4*)g_Q;
        float4 wp = *(const float4*)&g_w1p[c0];
        float4 wa = *(const float4*)&g_w1a[c0];
        float4 wb = *(const float4*)&g_w1b[c0];
        float4 tt = *(const float4*)&g_t1[c0];
        const float* of0p = Of + ((size_t)(b*2+0)*NUMK + k)*NN + n0;
        const float* of1p = Of + ((size_t)(b*2+1)*NUMK + k)*NN + n0;
        #pragma unroll
        for (int u = 0; u < 8; u++) {
            int s = sg + 32*u;
            int n = n0 + s;
            int j = jj[s];
            float4 p = __ldg(P4 + (size_t)(b*NN + n)*8 + cg);
            float4 q = __ldg(Q4 + (size_t)(b*NN + j)*8 + cg);
            float pf = pfv[s];
            float o0 = __ldg(of0p + s);
            float o1 = __ldg(of1p + s);
            float z0 = p.x + q.x + wp.x*pf + wa.x*o0 + wb.x*o1 + tt.x;
            float z1v= p.y + q.y + wp.y*pf + wa.y*o0 + wb.y*o1 + tt.y;
            float z2 = p.z + q.z + wp.z*pf + wa.z*o0 + wb.z*o1 + tt.z;
            float z3 = p.w + q.w + wp.w*pf + wa.w*o0 + wb.w*o1 + tt.w;
            buf0[(c0+0)*TS+s] = gelu_f(z0);
            buf0[(c0+1)*TS+s] = gelu_f(z1v);
            buf0[(c0+2)*TS+s] = gelu_f(z2);
            buf0[(c0+3)*TS+s] = gelu_f(z3);
        }
    }
    __syncthreads();

    mlp_layer<false>(buf0, buf1, g_W2t, g_t2, nullptr, cg, sg);  // h2 = gelu(bn2(W2 h1))
    __syncthreads();
    mlp_layer<false>(buf1, buf2, g_W3t, g_t3, nullptr, cg, sg);  // l3 = gelu(bn3(W3 h2))
    __syncthreads();
    mlp_layer<true >(buf2, buf0, g_W4t, g_t4, buf1,    cg, sg);  // XF = gelu(h2 + bn4(W4 l3))
    __syncthreads();

    // stage 5: head (3x32), U and Omega logits
    {
        int s = tid;
        float a = 0.f, be = 0.f, om = 0.f;
        #pragma unroll
        for (int c = 0; c < 32; c++) {
            float x = buf0[c*TS + s];
            a  += g_wcA[c]*x;
            be += g_wcB[c]*x;
            om += g_wcC[c]*x;
        }
        a  += g_bcv[0];
        be += g_bcv[1];
        om += g_bcv[2];
        float U = (a + 1.0f)*pfv[s] + be;
        size_t o = ((size_t)(b*NUMK + k))*NN + n0 + s;
        g_U[o]  = U;
        g_Om[o] = om;
    }
}

// ---------------- kernel 4: softmax over NUM + weighted sum ----------------
__global__ void epi_kernel(float* __restrict__ out)
{
    int gid = blockIdx.x * blockDim.x + threadIdx.x;
    if (gid >= BB*NN) return;
    int b = gid / NN, n = gid % NN;
    size_t base = (size_t)b*NUMK*NN + n;
    float om[NUMK];
    float m = -3.4e38f;
    #pragma unroll
    for (int k = 0; k < NUMK; k++) {
        om[k] = g_Om[base + (size_t)k*NN];
        m = fmaxf(m, om[k]);
    }
    float num = 0.f, den = 0.f;
    #pragma unroll
    for (int k = 0; k < NUMK; k++) {
        float e = expf(om[k] - m);
        den += e;
        num += e * g_U[base + (size_t)k*NN];
    }
    out[gid] = num / den;
}

// ---------------- launch ----------------
extern "C" void kernel_launch(void* const* d_in, const int* in_sizes, int n_in,
                              void* d_out, int out_size)
{
    const float* If = (const float*)d_in[0];
    const float* Pf = (const float*)d_in[1];
    const float* Of = (const float*)d_in[2];
    const void*  args = d_in[3];
    const float* W1 = (const float*)d_in[4];
    const float* g1 = (const float*)d_in[5];
    const float* b1 = (const float*)d_in[6];
    const float* m1 = (const float*)d_in[7];
    const float* v1 = (const float*)d_in[8];
    const float* W2 = (const float*)d_in[9];
    const float* g2 = (const float*)d_in[10];
    const float* b2 = (const float*)d_in[11];
    const float* m2 = (const float*)d_in[12];
    const float* v2 = (const float*)d_in[13];
    const float* W3 = (const float*)d_in[14];
    const float* g3 = (const float*)d_in[15];
    const float* b3 = (const float*)d_in[16];
    const float* m3 = (const float*)d_in[17];
    const float* v3 = (const float*)d_in[18];
    const float* W4 = (const float*)d_in[19];
    const float* g4 = (const float*)d_in[20];
    const float* b4 = (const float*)d_in[21];
    const float* m4 = (const float*)d_in[22];
    const float* v4 = (const float*)d_in[23];
    const float* Wc = (const float*)d_in[24];
    const float* bc = (const float*)d_in[25];

    prep_kernel<<<1, 256>>>(W1, g1, b1, m1, v1,
                            W2, g2, b2, m2, v2,
                            W3, g3, b3, m3, v3,
                            W4, g4, b4, m4, v4,
                            Wc, bc, (const int*)args);

    pq_kernel<<<BB*NT, 256>>>(If);

    const int dyn_smem = 25088 * 4;  // 100,352 B -> 2 blocks/SM
    cudaFuncSetAttribute(main_kernel, cudaFuncAttributeMaxDynamicSharedMemorySize, dyn_smem);
    main_kernel<<<BB*NUMK*NT, 256, dyn_smem>>>(Pf, Of, args);

    epi_kernel<<<(BB*NN + 255)/256, 256>>>((float*)d_out);
}